// round 16
// baseline (speedup 1.0000x reference)
#include <cuda_runtime.h>
#include <cuda_fp16.h>
#include <math.h>
#include <stdint.h>

#define NT 896
#define TILE 448
#define GRID_CTAS 152
#define XSTRIDE 456   // uint2 row stride: 456*8 mod 256 == 64 -> t-groups tile 256B, conflict-free

// smem: XI (uint2, fp16) | B1I/B2I/B3I (uint2, fp16) | misc floats
#define XI_N   (2 * 4 * XSTRIDE)          // uint2 count
#define B1I_N  2560                        // uint2 count
#define B2I_N  1024
#define B3I_N  512
#define MISC_F 544
#define SMEM_BYTES ((XI_N + B1I_N + B2I_N + B3I_N) * 8 + MISC_F * 4)
// misc float offsets
#define F_LNG  0
#define F_LNB  64
#define F_BB1  128
#define F_BB2  192
#define F_CEN  224
#define F_RW   352
#define F_RB   480
#define F_CS   488
#define F_BB1H 496   // 32 x uint32: b1 pairs packed fp16x2

__device__ __forceinline__ uint32_t pack_f16(float v0, float v1) {
    uint32_t h;
    asm("cvt.rn.f16x2.f32 %0, %1, %2;" : "=r"(h) : "f"(v1), "f"(v0));
    return h;
}
__device__ __forceinline__ uint32_t h2mul(uint32_t a, uint32_t b) {
    uint32_t d; asm("mul.rn.f16x2 %0, %1, %2;" : "=r"(d) : "r"(a), "r"(b)); return d;
}
__device__ __forceinline__ uint32_t h2add(uint32_t a, uint32_t b) {
    uint32_t d; asm("add.rn.f16x2 %0, %1, %2;" : "=r"(d) : "r"(a), "r"(b)); return d;
}
__device__ __forceinline__ uint32_t h2fma(uint32_t a, uint32_t b, uint32_t c) {
    uint32_t d; asm("fma.rn.f16x2 %0, %1, %2, %3;" : "=r"(d) : "r"(a), "r"(b), "r"(c)); return d;
}
// tanh-form gelu on a packed fp16x2 pair: 0.5x(1+tanh(x(c0+c1 x^2)))
__device__ __forceinline__ uint32_t gelu_h2(uint32_t x, uint32_t c0, uint32_t c1, uint32_t chalf) {
    uint32_t x2 = h2mul(x, x);
    uint32_t p  = h2fma(c1, x2, c0);
    uint32_t inner = h2mul(x, p);
    uint32_t th;
    asm("tanh.approx.f16x2 %0, %1;" : "=r"(th) : "r"(inner));
    uint32_t q = h2fma(th, chalf, chalf);
    return h2mul(x, q);
}
__device__ __forceinline__ void mma_f16(float* c, const uint32_t* a, uint32_t b0, uint32_t b1) {
    asm volatile(
        "mma.sync.aligned.m16n8k16.row.col.f32.f16.f16.f32 "
        "{%0,%1,%2,%3}, {%4,%5,%6,%7}, {%8,%9}, {%0,%1,%2,%3};"
        : "+f"(c[0]), "+f"(c[1]), "+f"(c[2]), "+f"(c[3])
        : "r"(a[0]), "r"(a[1]), "r"(a[2]), "r"(a[3]), "r"(b0), "r"(b1));
}
__device__ __forceinline__ float b1val(int k, int h,
    const float* __restrict__ chart_w, const float* __restrict__ tex_w,
    const float* __restrict__ chart_b, const float* __restrict__ tex_b) {
    if (k < 128)  return chart_w[(k >> 4) * 1024 + h * 16 + (k & 15)];
    if (k < 144)  return tex_w[h * 16 + (k - 128)];
    if (k < 152)  return chart_b[(k - 144) * 64 + h];
    if (k == 152) return tex_b[h];
    return 0.0f;
}

__global__ __launch_bounds__(NT)
void topo_decoder_mma13(
    const float* __restrict__ z_geo, const float* __restrict__ z_tex,
    const float* __restrict__ chart_w, const float* __restrict__ chart_b,
    const float* __restrict__ router_w, const float* __restrict__ router_b,
    const float* __restrict__ centers,
    const float* __restrict__ tex_w, const float* __restrict__ tex_b,
    const float* __restrict__ ln_g, const float* __restrict__ ln_b,
    const float* __restrict__ w1, const float* __restrict__ b1,
    const float* __restrict__ w2, const float* __restrict__ b2,
    float* __restrict__ out, int B)
{
    extern __shared__ uint2 smu2[];
    uint2* XI  = smu2;
    uint2* B1I = XI + XI_N;
    uint2* B2I = B1I + B1I_N;
    uint2* B3I = B2I + B2I_N;
    float* smf = (float*)(B3I + B3I_N);
    uint32_t* smw = (uint32_t*)smf;

    const int tid = threadIdx.x;
    const int wid = tid >> 5;
    const int lane = tid & 31;
    const int g = lane >> 2;
    const int t = lane & 3;

    const uint32_t GC0 = pack_f16(0.7978845608f, 0.7978845608f);
    const uint32_t GC1 = pack_f16(0.03567740814f, 0.03567740814f);
    const uint32_t GHF = pack_f16(0.5f, 0.5f);

    // ================== one-time weight packing (fp16) ==================
    for (int idx = tid; idx < B1I_N; idx += NT) {
        int tt = idx & 3, n = (idx >> 2) & 63, ks = idx >> 8;
        int k0 = ks * 16 + 2 * tt;
        uint2 q;
        q.x = pack_f16(b1val(k0,     n, chart_w, tex_w, chart_b, tex_b),
                       b1val(k0 + 1, n, chart_w, tex_w, chart_b, tex_b));
        q.y = pack_f16(b1val(k0 + 8, n, chart_w, tex_w, chart_b, tex_b),
                       b1val(k0 + 9, n, chart_w, tex_w, chart_b, tex_b));
        B1I[idx] = q;
    }
    for (int idx = tid; idx < B2I_N; idx += NT) {
        int tt = idx & 3, n = (idx >> 2) & 63, ks = idx >> 8;
        int k0 = ks * 16 + 2 * tt;
        uint2 q;
        q.x = pack_f16(w1[n * 64 + k0],     w1[n * 64 + k0 + 1]);
        q.y = pack_f16(w1[n * 64 + k0 + 8], w1[n * 64 + k0 + 9]);
        B2I[idx] = q;
    }
    for (int idx = tid; idx < B3I_N; idx += NT) {
        int tt = idx & 3, n = (idx >> 2) & 31, ks = idx >> 7;
        int k0 = ks * 16 + 2 * tt;
        uint2 q;
        q.x = pack_f16(w2[n * 64 + k0],     w2[n * 64 + k0 + 1]);
        q.y = pack_f16(w2[n * 64 + k0 + 8], w2[n * 64 + k0 + 9]);
        B3I[idx] = q;
    }
    if (tid < 64) {
        smf[F_LNG + tid] = ln_g[tid];
        smf[F_LNB + tid] = ln_b[tid];
        smf[F_BB1 + tid] = b1[tid];
    }
    if (tid < 32) {
        smf[F_BB2 + tid] = b2[tid];
        smw[F_BB1H + tid] = pack_f16(b1[2 * tid], b1[2 * tid + 1]);
    }
    if (tid < 128) { smf[F_CEN + tid] = centers[tid]; smf[F_RW + tid] = router_w[tid]; }
    if (tid < 8) {
        smf[F_RB + tid] = router_b[tid];
        float cs = 0.f;
        for (int l = 0; l < 16; ++l) cs = fmaf(centers[tid * 16 + l], centers[tid * 16 + l], cs);
        smf[F_CS + tid] = 1.0f - cs;
    }
    __syncthreads();

    const int nTiles = (B + TILE - 1) / TILE;
    const int xcol = wid * 16;
    const int rl = tid >> 1;          // staging row-in-tile
    const int half = tid & 1;

    for (int tile = blockIdx.x; tile < nTiles; tile += GRID_CTAS) {
        const int rowbase = tile * TILE + xcol;
        const int rawrow = tile * TILE + rl;
        const int srow = rawrow < B ? rawrow : (B - 1);

        // ================== prologue: split router ==================
        uint32_t zgh0, zgh1, zgh2, zgh3;   // this thread's zg slice, fp16x2
        float w8[8];
        {
            float zg[16];
            const float4* p = (const float4*)(z_geo + (size_t)srow * 16);
            #pragma unroll
            for (int q = 0; q < 4; ++q) {
                float4 v = p[q];
                zg[q*4+0]=v.x; zg[q*4+1]=v.y; zg[q*4+2]=v.z; zg[q*4+3]=v.w;
            }
            float z_sq = 0.f;
            #pragma unroll
            for (int l = 0; l < 16; ++l) z_sq = fmaf(zg[l], zg[l], z_sq);
            const float one_minus = 1.0f - z_sq;
            const float inv_tau = __fdividef(1.0f, fmaxf(2.0f * fmaxf(one_minus, 0.001f), 0.01f));

            const int cb = half * 4;
            float s[4], mx = -1e30f;
            #pragma unroll
            for (int i = 0; i < 4; ++i) {
                const int c = cb + i;
                float ds = 0.f, dr = 0.f;
                #pragma unroll
                for (int l = 0; l < 16; ++l) {
                    float cv = smf[F_CEN + c * 16 + l];
                    float d = zg[l] - cv;
                    ds = fmaf(d, d, ds);
                    dr = fmaf(zg[l], smf[F_RW + c * 16 + l], dr);
                }
                float denom = one_minus * smf[F_CS + c];
                float tt2 = fmaxf(2.0f * __fdividef(ds, denom + 0.001f), 0.001f);
                float rad = tt2 * (tt2 + 2.0f);
                float sq = rad * rsqrtf(rad);
                float dist = __logf(1.0f + tt2 + sq);
                s[i] = (-dist + 0.1f * (dr + smf[F_RB + c])) * inv_tau;
                mx = fmaxf(mx, s[i]);
            }
            mx = fmaxf(mx, __shfl_xor_sync(~0u, mx, 1));
            float wloc[4], psum = 0.f;
            #pragma unroll
            for (int i = 0; i < 4; ++i) { wloc[i] = __expf(s[i] - mx); psum += wloc[i]; }
            float ssum = psum + __shfl_xor_sync(~0u, psum, 1);
            const float inv_sum = __fdividef(1.0f, ssum);
            #pragma unroll
            for (int i = 0; i < 4; ++i) {
                float wi = wloc[i] * inv_sum;
                w8[cb + i] = wi;
                w8[(cb ^ 4) + i] = __shfl_xor_sync(~0u, wi, 1);
            }
            if (rawrow < B) {
                float* rout = out + (size_t)B * 32 + (size_t)rawrow * 8 + cb;
                *(float4*)rout = make_float4(w8[cb], w8[cb+1], w8[cb+2], w8[cb+3]);
            }
            zgh0 = pack_f16(zg[4*half + 0], zg[4*half + 1]);
            zgh1 = pack_f16(zg[4*half + 2], zg[4*half + 3]);
            zgh2 = pack_f16(zg[4*half + 8], zg[4*half + 9]);
            zgh3 = pack_f16(zg[4*half + 10], zg[4*half + 11]);
        }
        // prefetch zt slice this thread stages (ks 8)
        float4 ztA = *(const float4*)(z_tex + (size_t)srow * 16 + 4 * half);
        float4 ztB = *(const float4*)(z_tex + (size_t)srow * 16 + 4 * half + 8);
        const float wa0 = half ? w8[4] : w8[0];
        const float wa1 = half ? w8[5] : w8[1];
        const float wb0 = half ? w8[6] : w8[2];
        const float wb1 = half ? w8[7] : w8[3];

        // ================== GEMM1: 2-slot ring over ks (fp16) ==========
        float acc[8][4];
        #pragma unroll
        for (int nb = 0; nb < 8; ++nb)
            #pragma unroll
            for (int j = 0; j < 4; ++j) acc[nb][j] = 0.f;

        #pragma unroll
        for (int p = 0; p < 10; ++p) {
            const int slot = p & 1;
            if (p < 8) {
                const uint32_t wch = pack_f16(w8[p], w8[p]);
                uint2 q0, q1;
                q0.x = h2mul(wch, zgh0); q0.y = h2mul(wch, zgh2);
                q1.x = h2mul(wch, zgh1); q1.y = h2mul(wch, zgh3);
                XI[(slot * 4 + 2 * half)     * XSTRIDE + rl] = q0;
                XI[(slot * 4 + 2 * half + 1) * XSTRIDE + rl] = q1;
            } else if (p == 8) {
                uint2 q0, q1;
                q0.x = pack_f16(ztA.x, ztA.y); q0.y = pack_f16(ztB.x, ztB.y);
                q1.x = pack_f16(ztA.z, ztA.w); q1.y = pack_f16(ztB.z, ztB.w);
                XI[(slot * 4 + 2 * half)     * XSTRIDE + rl] = q0;
                XI[(slot * 4 + 2 * half + 1) * XSTRIDE + rl] = q1;
            } else {
                uint2 q0, q1;
                q0.x = pack_f16(wa0, wa1);
                q0.y = pack_f16(half ? 0.0f : 1.0f, 0.0f);
                q1.x = pack_f16(wb0, wb1);
                q1.y = 0u;
                XI[(slot * 4 + 2 * half)     * XSTRIDE + rl] = q0;
                XI[(slot * 4 + 2 * half + 1) * XSTRIDE + rl] = q1;
            }
            __syncwarp();
            uint2 qa = XI[(slot * 4 + t) * XSTRIDE + xcol + g];
            uint2 qb = XI[(slot * 4 + t) * XSTRIDE + xcol + g + 8];
            uint32_t ah[4] = { qa.x, qb.x, qa.y, qb.y };
            #pragma unroll
            for (int nb = 0; nb < 8; ++nb) {
                uint2 qB = B1I[(p * 64 + nb * 8 + g) * 4 + t];
                mma_f16(acc[nb], ah, qB.x, qB.y);
            }
        }
        __syncwarp();

        // ================== epilogue 1: LayerNorm + GELU(h2) -> A2 frags =====
        uint32_t a2h[4][4];
        {
            float sum0 = 0.f, sum1 = 0.f, sq0 = 0.f, sq1 = 0.f;
            #pragma unroll
            for (int nb = 0; nb < 8; ++nb) {
                sum0 += acc[nb][0] + acc[nb][1];
                sum1 += acc[nb][2] + acc[nb][3];
                sq0 = fmaf(acc[nb][0], acc[nb][0], sq0); sq0 = fmaf(acc[nb][1], acc[nb][1], sq0);
                sq1 = fmaf(acc[nb][2], acc[nb][2], sq1); sq1 = fmaf(acc[nb][3], acc[nb][3], sq1);
            }
            sum0 += __shfl_xor_sync(~0u, sum0, 1); sum0 += __shfl_xor_sync(~0u, sum0, 2);
            sum1 += __shfl_xor_sync(~0u, sum1, 1); sum1 += __shfl_xor_sync(~0u, sum1, 2);
            sq0  += __shfl_xor_sync(~0u, sq0, 1);  sq0  += __shfl_xor_sync(~0u, sq0, 2);
            sq1  += __shfl_xor_sync(~0u, sq1, 1);  sq1  += __shfl_xor_sync(~0u, sq1, 2);
            const float mu0 = sum0 * (1.0f / 64.0f), mu1 = sum1 * (1.0f / 64.0f);
            const float rstd0 = rsqrtf(fmaf(-mu0, mu0, sq0 * (1.0f / 64.0f)) + 1e-5f);
            const float rstd1 = rsqrtf(fmaf(-mu1, mu1, sq1 * (1.0f / 64.0f)) + 1e-5f);
            const float nm0 = -mu0 * rstd0, nm1 = -mu1 * rstd1;

            #pragma unroll
            for (int ks = 0; ks < 4; ++ks) {
                #pragma unroll
                for (int jj = 0; jj < 2; ++jj) {
                    int nb = 2 * ks + jj;
                    int col = nb * 8 + 2 * t;
                    float g0 = smf[F_LNG + col], g1 = smf[F_LNG + col + 1];
                    float e0 = smf[F_LNB + col], e1 = smf[F_LNB + col + 1];
                    float t00 = fmaf(acc[nb][0], rstd0, nm0);
                    float t01 = fmaf(acc[nb][1], rstd0, nm0);
                    float t10 = fmaf(acc[nb][2], rstd1, nm1);
                    float t11 = fmaf(acc[nb][3], rstd1, nm1);
                    uint32_t u0 = pack_f16(fmaf(t00, g0, e0), fmaf(t01, g1, e1));
                    uint32_t u1 = pack_f16(fmaf(t10, g0, e0), fmaf(t11, g1, e1));
                    a2h[ks][2*jj]     = gelu_h2(u0, GC0, GC1, GHF);
                    a2h[ks][2*jj + 1] = gelu_h2(u1, GC0, GC1, GHF);
                }
            }
        }

        // ================== GEMM2: [16x64] x [64x64] (fp16) ============
        #pragma unroll
        for (int nb = 0; nb < 8; ++nb)
            #pragma unroll
            for (int j = 0; j < 4; ++j) acc[nb][j] = 0.f;
        #pragma unroll
        for (int ks = 0; ks < 4; ++ks) {
            #pragma unroll
            for (int nb = 0; nb < 8; ++nb) {
                uint2 qB = B2I[(ks * 64 + nb * 8 + g) * 4 + t];
                mma_f16(acc[nb], a2h[ks], qB.x, qB.y);
            }
        }

        // ================== epilogue 2: +b1(h2), GELU(h2) -> A3 frags ===========
        uint32_t a3h[4][4];
        #pragma unroll
        for (int ks = 0; ks < 4; ++ks) {
            #pragma unroll
            for (int jj = 0; jj < 2; ++jj) {
                int nb = 2 * ks + jj;
                uint32_t bb = smw[F_BB1H + nb * 4 + t];
                uint32_t u0 = h2add(pack_f16(acc[nb][0], acc[nb][1]), bb);
                uint32_t u1 = h2add(pack_f16(acc[nb][2], acc[nb][3]), bb);
                a3h[ks][2*jj]     = gelu_h2(u0, GC0, GC1, GHF);
                a3h[ks][2*jj + 1] = gelu_h2(u1, GC0, GC1, GHF);
            }
        }

        // ================== GEMM3: [16x64] x [64x32] (fp16) ============
        float acc3[4][4];
        #pragma unroll
        for (int nb = 0; nb < 4; ++nb)
            #pragma unroll
            for (int j = 0; j < 4; ++j) acc3[nb][j] = 0.f;
        #pragma unroll
        for (int ks = 0; ks < 4; ++ks) {
            #pragma unroll
            for (int nb = 0; nb < 4; ++nb) {
                uint2 qB = B3I[(ks * 32 + nb * 8 + g) * 4 + t];
                mma_f16(acc3[nb], a3h[ks], qB.x, qB.y);
            }
        }

        // ================== epilogue 3: +b2 -> out ==================
        #pragma unroll
        for (int nb = 0; nb < 4; ++nb) {
            int col = nb * 8 + 2 * t;
            float b20 = smf[F_BB2 + col], b21 = smf[F_BB2 + col + 1];
            if (rowbase + g < B)
                *(float2*)(out + (size_t)(rowbase + g) * 32 + col) =
                    make_float2(acc3[nb][0] + b20, acc3[nb][1] + b21);
            if (rowbase + g + 8 < B)
                *(float2*)(out + (size_t)(rowbase + g + 8) * 32 + col) =
                    make_float2(acc3[nb][2] + b20, acc3[nb][3] + b21);
        }
        __syncwarp();
    }
}

extern "C" void kernel_launch(void* const* d_in, const int* in_sizes, int n_in,
                              void* d_out, int out_size) {
    const float* z_geo    = (const float*)d_in[0];
    const float* z_tex    = (const float*)d_in[1];
    const float* chart_w  = (const float*)d_in[2];
    const float* chart_b  = (const float*)d_in[3];
    const float* router_w = (const float*)d_in[4];
    const float* router_b = (const float*)d_in[5];
    const float* centers  = (const float*)d_in[6];
    const float* tex_w    = (const float*)d_in[7];
    const float* tex_b    = (const float*)d_in[8];
    const float* ln_g     = (const float*)d_in[9];
    const float* ln_b     = (const float*)d_in[10];
    const float* w1       = (const float*)d_in[11];
    const float* b1       = (const float*)d_in[12];
    const float* w2       = (const float*)d_in[13];
    const float* b2       = (const float*)d_in[14];
    float* out = (float*)d_out;

    const int B = in_sizes[0] / 16;
    cudaFuncSetAttribute(topo_decoder_mma13,
                         cudaFuncAttributeMaxDynamicSharedMemorySize, SMEM_BYTES);
    topo_decoder_mma13<<<GRID_CTAS, NT, SMEM_BYTES>>>(
        z_geo, z_tex, chart_w, chart_b, router_w, router_b, centers,
        tex_w, tex_b, ln_g, ln_b, w1, b1, w2, b2, out, B);
}

// round 17
// speedup vs baseline: 1.0842x; 1.0842x over previous
#include <cuda_runtime.h>
#include <cuda_fp16.h>
#include <math.h>
#include <stdint.h>

#define NT 576
#define TILE 576
#define GRID_CTAS 152
#define XSTRIDE 584   // uint2 row stride (TILE+8)

// smem: XI (uint2, fp16) | B1I/B2I/B3I (uint2, fp16) | misc floats
#define XI_N   (2 * 4 * XSTRIDE)          // uint2 count
#define B1I_N  2560                        // uint2 count
#define B2I_N  1024
#define B3I_N  512
#define MISC_F 544
#define SMEM_BYTES ((XI_N + B1I_N + B2I_N + B3I_N) * 8 + MISC_F * 4)
// misc float offsets
#define F_LNG  0
#define F_LNB  64
#define F_BB1  128
#define F_BB2  192
#define F_CEN  224
#define F_RW   352
#define F_RB   480
#define F_CS   488
#define F_BB1H 496   // 32 x uint32: b1 pairs packed fp16x2

__device__ __forceinline__ uint32_t pack_f16(float v0, float v1) {
    uint32_t h;
    asm("cvt.rn.f16x2.f32 %0, %1, %2;" : "=r"(h) : "f"(v1), "f"(v0));
    return h;
}
__device__ __forceinline__ uint32_t h2mul(uint32_t a, uint32_t b) {
    uint32_t d; asm("mul.rn.f16x2 %0, %1, %2;" : "=r"(d) : "r"(a), "r"(b)); return d;
}
__device__ __forceinline__ uint32_t h2add(uint32_t a, uint32_t b) {
    uint32_t d; asm("add.rn.f16x2 %0, %1, %2;" : "=r"(d) : "r"(a), "r"(b)); return d;
}
__device__ __forceinline__ uint32_t h2fma(uint32_t a, uint32_t b, uint32_t c) {
    uint32_t d; asm("fma.rn.f16x2 %0, %1, %2, %3;" : "=r"(d) : "r"(a), "r"(b), "r"(c)); return d;
}
// tanh-form gelu on a packed fp16x2 pair: 0.5x(1+tanh(x(c0+c1 x^2)))
__device__ __forceinline__ uint32_t gelu_h2(uint32_t x, uint32_t c0, uint32_t c1, uint32_t chalf) {
    uint32_t x2 = h2mul(x, x);
    uint32_t p  = h2fma(c1, x2, c0);
    uint32_t inner = h2mul(x, p);
    uint32_t th;
    asm("tanh.approx.f16x2 %0, %1;" : "=r"(th) : "r"(inner));
    uint32_t q = h2fma(th, chalf, chalf);
    return h2mul(x, q);
}
__device__ __forceinline__ void mma_f16(float* c, const uint32_t* a, uint32_t b0, uint32_t b1) {
    asm volatile(
        "mma.sync.aligned.m16n8k16.row.col.f32.f16.f16.f32 "
        "{%0,%1,%2,%3}, {%4,%5,%6,%7}, {%8,%9}, {%0,%1,%2,%3};"
        : "+f"(c[0]), "+f"(c[1]), "+f"(c[2]), "+f"(c[3])
        : "r"(a[0]), "r"(a[1]), "r"(a[2]), "r"(a[3]), "r"(b0), "r"(b1));
}
__device__ __forceinline__ float b1val(int k, int h,
    const float* __restrict__ chart_w, const float* __restrict__ tex_w,
    const float* __restrict__ chart_b, const float* __restrict__ tex_b) {
    if (k < 128)  return chart_w[(k >> 4) * 1024 + h * 16 + (k & 15)];
    if (k < 144)  return tex_w[h * 16 + (k - 128)];
    if (k < 152)  return chart_b[(k - 144) * 64 + h];
    if (k == 152) return tex_b[h];
    return 0.0f;
}

__global__ __launch_bounds__(NT)
void topo_decoder_mma14(
    const float* __restrict__ z_geo, const float* __restrict__ z_tex,
    const float* __restrict__ chart_w, const float* __restrict__ chart_b,
    const float* __restrict__ router_w, const float* __restrict__ router_b,
    const float* __restrict__ centers,
    const float* __restrict__ tex_w, const float* __restrict__ tex_b,
    const float* __restrict__ ln_g, const float* __restrict__ ln_b,
    const float* __restrict__ w1, const float* __restrict__ b1,
    const float* __restrict__ w2, const float* __restrict__ b2,
    float* __restrict__ out, int B)
{
    extern __shared__ uint2 smu2[];
    uint2* XI  = smu2;
    uint2* B1I = XI + XI_N;
    uint2* B2I = B1I + B1I_N;
    uint2* B3I = B2I + B2I_N;
    float* smf = (float*)(B3I + B3I_N);
    uint32_t* smw = (uint32_t*)smf;

    const int tid = threadIdx.x;
    const int wid = tid >> 5;
    const int lane = tid & 31;
    const int g = lane >> 2;
    const int t = lane & 3;

    const uint32_t GC0 = pack_f16(0.7978845608f, 0.7978845608f);
    const uint32_t GC1 = pack_f16(0.03567740814f, 0.03567740814f);
    const uint32_t GHF = pack_f16(0.5f, 0.5f);

    // ================== one-time weight packing (fp16) ==================
    for (int idx = tid; idx < B1I_N; idx += NT) {
        int tt = idx & 3, n = (idx >> 2) & 63, ks = idx >> 8;
        int k0 = ks * 16 + 2 * tt;
        uint2 q;
        q.x = pack_f16(b1val(k0,     n, chart_w, tex_w, chart_b, tex_b),
                       b1val(k0 + 1, n, chart_w, tex_w, chart_b, tex_b));
        q.y = pack_f16(b1val(k0 + 8, n, chart_w, tex_w, chart_b, tex_b),
                       b1val(k0 + 9, n, chart_w, tex_w, chart_b, tex_b));
        B1I[idx] = q;
    }
    for (int idx = tid; idx < B2I_N; idx += NT) {
        int tt = idx & 3, n = (idx >> 2) & 63, ks = idx >> 8;
        int k0 = ks * 16 + 2 * tt;
        uint2 q;
        q.x = pack_f16(w1[n * 64 + k0],     w1[n * 64 + k0 + 1]);
        q.y = pack_f16(w1[n * 64 + k0 + 8], w1[n * 64 + k0 + 9]);
        B2I[idx] = q;
    }
    for (int idx = tid; idx < B3I_N; idx += NT) {
        int tt = idx & 3, n = (idx >> 2) & 31, ks = idx >> 7;
        int k0 = ks * 16 + 2 * tt;
        uint2 q;
        q.x = pack_f16(w2[n * 64 + k0],     w2[n * 64 + k0 + 1]);
        q.y = pack_f16(w2[n * 64 + k0 + 8], w2[n * 64 + k0 + 9]);
        B3I[idx] = q;
    }
    if (tid < 64) {
        smf[F_LNG + tid] = ln_g[tid];
        smf[F_LNB + tid] = ln_b[tid];
        smf[F_BB1 + tid] = b1[tid];
    }
    if (tid < 32) {
        smf[F_BB2 + tid] = b2[tid];
        smw[F_BB1H + tid] = pack_f16(b1[2 * tid], b1[2 * tid + 1]);
    }
    if (tid < 128) { smf[F_CEN + tid] = centers[tid]; smf[F_RW + tid] = router_w[tid]; }
    if (tid < 8) {
        smf[F_RB + tid] = router_b[tid];
        float cs = 0.f;
        for (int l = 0; l < 16; ++l) cs = fmaf(centers[tid * 16 + l], centers[tid * 16 + l], cs);
        smf[F_CS + tid] = 1.0f - cs;
    }
    __syncthreads();

    const int nTiles = (B + TILE - 1) / TILE;
    const int xcol = wid * 32;        // this warp's 32 rows

    for (int tile = blockIdx.x; tile < nTiles; tile += GRID_CTAS) {
        const int rowbase = tile * TILE + xcol;
        const int rawrow = tile * TILE + tid;               // staging: 1 thread per row
        const int srow = rawrow < B ? rawrow : (B - 1);

        // ================== prologue: full router per thread ==================
        uint32_t zgh[8];
        float w8[8];
        {
            float zg[16];
            const float4* p = (const float4*)(z_geo + (size_t)srow * 16);
            #pragma unroll
            for (int q = 0; q < 4; ++q) {
                float4 v = p[q];
                zg[q*4+0]=v.x; zg[q*4+1]=v.y; zg[q*4+2]=v.z; zg[q*4+3]=v.w;
            }
            float z_sq = 0.f;
            #pragma unroll
            for (int l = 0; l < 16; ++l) z_sq = fmaf(zg[l], zg[l], z_sq);
            const float one_minus = 1.0f - z_sq;
            const float inv_tau = __fdividef(1.0f, fmaxf(2.0f * fmaxf(one_minus, 0.001f), 0.01f));

            float mx = -1e30f;
            #pragma unroll
            for (int c = 0; c < 8; ++c) {
                float ds = 0.f, dr = 0.f;
                #pragma unroll
                for (int l = 0; l < 16; ++l) {
                    float cv = smf[F_CEN + c * 16 + l];
                    float d = zg[l] - cv;
                    ds = fmaf(d, d, ds);
                    dr = fmaf(zg[l], smf[F_RW + c * 16 + l], dr);
                }
                float denom = one_minus * smf[F_CS + c];
                float tt2 = fmaxf(2.0f * __fdividef(ds, denom + 0.001f), 0.001f);
                float rad = tt2 * (tt2 + 2.0f);
                float sq = rad * rsqrtf(rad);
                float dist = __logf(1.0f + tt2 + sq);
                w8[c] = (-dist + 0.1f * (dr + smf[F_RB + c])) * inv_tau;
                mx = fmaxf(mx, w8[c]);
            }
            float ssum = 0.f;
            #pragma unroll
            for (int c = 0; c < 8; ++c) { w8[c] = __expf(w8[c] - mx); ssum += w8[c]; }
            const float inv_sum = __fdividef(1.0f, ssum);
            #pragma unroll
            for (int c = 0; c < 8; ++c) w8[c] *= inv_sum;

            if (rawrow < B) {
                float* rout = out + (size_t)B * 32 + (size_t)rawrow * 8;
                ((float4*)rout)[0] = make_float4(w8[0], w8[1], w8[2], w8[3]);
                ((float4*)rout)[1] = make_float4(w8[4], w8[5], w8[6], w8[7]);
            }
            #pragma unroll
            for (int j = 0; j < 8; ++j) zgh[j] = pack_f16(zg[2*j], zg[2*j+1]);
        }

        // ================== GEMM1: 2-slot ring over ks, 2 m-blocks ==========
        float acc[2][8][4];
        #pragma unroll
        for (int mb = 0; mb < 2; ++mb)
            #pragma unroll
            for (int nb = 0; nb < 8; ++nb)
                #pragma unroll
                for (int j = 0; j < 4; ++j) acc[mb][nb][j] = 0.f;

        #pragma unroll
        for (int p = 0; p < 10; ++p) {
            const int slot = p & 1;
            // ---- stage ks p: this thread stages its full row (4 tt slots) ----
            if (p < 8) {
                const uint32_t wch = pack_f16(w8[p], w8[p]);
                #pragma unroll
                for (int tt = 0; tt < 4; ++tt) {
                    uint2 q;
                    q.x = h2mul(wch, zgh[tt]);
                    q.y = h2mul(wch, zgh[tt + 4]);
                    XI[(slot * 4 + tt) * XSTRIDE + tid] = q;
                }
            } else if (p == 8) {
                // lazy z_tex load (frees 8 regs across GEMM1)
                const float4* p2 = (const float4*)(z_tex + (size_t)srow * 16);
                float4 v0 = p2[0], v1 = p2[1], v2 = p2[2], v3 = p2[3];
                uint32_t zt0 = pack_f16(v0.x, v0.y), zt1 = pack_f16(v0.z, v0.w);
                uint32_t zt2 = pack_f16(v1.x, v1.y), zt3 = pack_f16(v1.z, v1.w);
                uint32_t zt4 = pack_f16(v2.x, v2.y), zt5 = pack_f16(v2.z, v2.w);
                uint32_t zt6 = pack_f16(v3.x, v3.y), zt7 = pack_f16(v3.z, v3.w);
                uint2 q;
                q.x = zt0; q.y = zt4; XI[(slot * 4 + 0) * XSTRIDE + tid] = q;
                q.x = zt1; q.y = zt5; XI[(slot * 4 + 1) * XSTRIDE + tid] = q;
                q.x = zt2; q.y = zt6; XI[(slot * 4 + 2) * XSTRIDE + tid] = q;
                q.x = zt3; q.y = zt7; XI[(slot * 4 + 3) * XSTRIDE + tid] = q;
            } else {
                const uint32_t one0 = pack_f16(1.0f, 0.0f);
                #pragma unroll
                for (int tt = 0; tt < 4; ++tt) {
                    uint2 q;
                    q.x = pack_f16(w8[2*tt], w8[2*tt+1]);
                    q.y = (tt == 0) ? one0 : 0u;
                    XI[(slot * 4 + tt) * XSTRIDE + tid] = q;
                }
            }
            __syncwarp();
            // ---- MMA ks p: shared B across both m-blocks ----
            uint2 qa0 = XI[(slot * 4 + t) * XSTRIDE + xcol + g];
            uint2 qb0 = XI[(slot * 4 + t) * XSTRIDE + xcol + g + 8];
            uint2 qa1 = XI[(slot * 4 + t) * XSTRIDE + xcol + 16 + g];
            uint2 qb1 = XI[(slot * 4 + t) * XSTRIDE + xcol + 16 + g + 8];
            uint32_t ah0[4] = { qa0.x, qb0.x, qa0.y, qb0.y };
            uint32_t ah1[4] = { qa1.x, qb1.x, qa1.y, qb1.y };
            #pragma unroll
            for (int nb = 0; nb < 8; ++nb) {
                uint2 qB = B1I[(p * 64 + nb * 8 + g) * 4 + t];
                mma_f16(acc[0][nb], ah0, qB.x, qB.y);
                mma_f16(acc[1][nb], ah1, qB.x, qB.y);
            }
        }
        __syncwarp();

        // ================== epilogue 1: LayerNorm + GELU(h2) -> A2 frags =====
        uint32_t a2h[2][4][4];
        #pragma unroll
        for (int mb = 0; mb < 2; ++mb) {
            float sum0 = 0.f, sum1 = 0.f, sq0 = 0.f, sq1 = 0.f;
            #pragma unroll
            for (int nb = 0; nb < 8; ++nb) {
                sum0 += acc[mb][nb][0] + acc[mb][nb][1];
                sum1 += acc[mb][nb][2] + acc[mb][nb][3];
                sq0 = fmaf(acc[mb][nb][0], acc[mb][nb][0], sq0);
                sq0 = fmaf(acc[mb][nb][1], acc[mb][nb][1], sq0);
                sq1 = fmaf(acc[mb][nb][2], acc[mb][nb][2], sq1);
                sq1 = fmaf(acc[mb][nb][3], acc[mb][nb][3], sq1);
            }
            sum0 += __shfl_xor_sync(~0u, sum0, 1); sum0 += __shfl_xor_sync(~0u, sum0, 2);
            sum1 += __shfl_xor_sync(~0u, sum1, 1); sum1 += __shfl_xor_sync(~0u, sum1, 2);
            sq0  += __shfl_xor_sync(~0u, sq0, 1);  sq0  += __shfl_xor_sync(~0u, sq0, 2);
            sq1  += __shfl_xor_sync(~0u, sq1, 1);  sq1  += __shfl_xor_sync(~0u, sq1, 2);
            const float mu0 = sum0 * (1.0f / 64.0f), mu1 = sum1 * (1.0f / 64.0f);
            const float rstd0 = rsqrtf(fmaf(-mu0, mu0, sq0 * (1.0f / 64.0f)) + 1e-5f);
            const float rstd1 = rsqrtf(fmaf(-mu1, mu1, sq1 * (1.0f / 64.0f)) + 1e-5f);
            const float nm0 = -mu0 * rstd0, nm1 = -mu1 * rstd1;

            #pragma unroll
            for (int ks = 0; ks < 4; ++ks) {
                #pragma unroll
                for (int jj = 0; jj < 2; ++jj) {
                    int nb = 2 * ks + jj;
                    int col = nb * 8 + 2 * t;
                    float g0 = smf[F_LNG + col], g1 = smf[F_LNG + col + 1];
                    float e0 = smf[F_LNB + col], e1 = smf[F_LNB + col + 1];
                    float t00 = fmaf(acc[mb][nb][0], rstd0, nm0);
                    float t01 = fmaf(acc[mb][nb][1], rstd0, nm0);
                    float t10 = fmaf(acc[mb][nb][2], rstd1, nm1);
                    float t11 = fmaf(acc[mb][nb][3], rstd1, nm1);
                    uint32_t u0 = pack_f16(fmaf(t00, g0, e0), fmaf(t01, g1, e1));
                    uint32_t u1 = pack_f16(fmaf(t10, g0, e0), fmaf(t11, g1, e1));
                    a2h[mb][ks][2*jj]     = gelu_h2(u0, GC0, GC1, GHF);
                    a2h[mb][ks][2*jj + 1] = gelu_h2(u1, GC0, GC1, GHF);
                }
            }
        }

        // ================== GEMM2: shared B across m-blocks ============
        #pragma unroll
        for (int mb = 0; mb < 2; ++mb)
            #pragma unroll
            for (int nb = 0; nb < 8; ++nb)
                #pragma unroll
                for (int j = 0; j < 4; ++j) acc[mb][nb][j] = 0.f;
        #pragma unroll
        for (int ks = 0; ks < 4; ++ks) {
            #pragma unroll
            for (int nb = 0; nb < 8; ++nb) {
                uint2 qB = B2I[(ks * 64 + nb * 8 + g) * 4 + t];
                mma_f16(acc[0][nb], a2h[0][ks], qB.x, qB.y);
                mma_f16(acc[1][nb], a2h[1][ks], qB.x, qB.y);
            }
        }

        // ================== epilogue 2: +b1(h2), GELU(h2) -> A3 frags ===========
        uint32_t a3h[2][4][4];
        #pragma unroll
        for (int mb = 0; mb < 2; ++mb) {
            #pragma unroll
            for (int ks = 0; ks < 4; ++ks) {
                #pragma unroll
                for (int jj = 0; jj < 2; ++jj) {
                    int nb = 2 * ks + jj;
                    uint32_t bb = smw[F_BB1H + nb * 4 + t];
                    uint32_t u0 = h2add(pack_f16(acc[mb][nb][0], acc[mb][nb][1]), bb);
                    uint32_t u1 = h2add(pack_f16(acc[mb][nb][2], acc[mb][nb][3]), bb);
                    a3h[mb][ks][2*jj]     = gelu_h2(u0, GC0, GC1, GHF);
                    a3h[mb][ks][2*jj + 1] = gelu_h2(u1, GC0, GC1, GHF);
                }
            }
        }

        // ================== GEMM3: shared B across m-blocks ============
        float acc3[2][4][4];
        #pragma unroll
        for (int mb = 0; mb < 2; ++mb)
            #pragma unroll
            for (int nb = 0; nb < 4; ++nb)
                #pragma unroll
                for (int j = 0; j < 4; ++j) acc3[mb][nb][j] = 0.f;
        #pragma unroll
        for (int ks = 0; ks < 4; ++ks) {
            #pragma unroll
            for (int nb = 0; nb < 4; ++nb) {
                uint2 qB = B3I[(ks * 32 + nb * 8 + g) * 4 + t];
                mma_f16(acc3[0][nb], a3h[0][ks], qB.x, qB.y);
                mma_f16(acc3[1][nb], a3h[1][ks], qB.x, qB.y);
            }
        }

        // ================== epilogue 3: +b2 -> out ==================
        #pragma unroll
        for (int mb = 0; mb < 2; ++mb) {
            const int rb = rowbase + mb * 16;
            #pragma unroll
            for (int nb = 0; nb < 4; ++nb) {
                int col = nb * 8 + 2 * t;
                float b20 = smf[F_BB2 + col], b21 = smf[F_BB2 + col + 1];
                if (rb + g < B)
                    *(float2*)(out + (size_t)(rb + g) * 32 + col) =
                        make_float2(acc3[mb][nb][0] + b20, acc3[mb][nb][1] + b21);
                if (rb + g + 8 < B)
                    *(float2*)(out + (size_t)(rb + g + 8) * 32 + col) =
                        make_float2(acc3[mb][nb][2] + b20, acc3[mb][nb][3] + b21);
            }
        }
        __syncwarp();
    }
}

extern "C" void kernel_launch(void* const* d_in, const int* in_sizes, int n_in,
                              void* d_out, int out_size) {
    const float* z_geo    = (const float*)d_in[0];
    const float* z_tex    = (const float*)d_in[1];
    const float* chart_w  = (const float*)d_in[2];
    const float* chart_b  = (const float*)d_in[3];
    const float* router_w = (const float*)d_in[4];
    const float* router_b = (const float*)d_in[5];
    const float* centers  = (const float*)d_in[6];
    const float* tex_w    = (const float*)d_in[7];
    const float* tex_b    = (const float*)d_in[8];
    const float* ln_g     = (const float*)d_in[9];
    const float* ln_b     = (const float*)d_in[10];
    const float* w1       = (const float*)d_in[11];
    const float* b1       = (const float*)d_in[12];
    const float* w2       = (const float*)d_in[13];
    const float* b2       = (const float*)d_in[14];
    float* out = (float*)d_out;

    const int B = in_sizes[0] / 16;
    cudaFuncSetAttribute(topo_decoder_mma14,
                         cudaFuncAttributeMaxDynamicSharedMemorySize, SMEM_BYTES);
    topo_decoder_mma14<<<GRID_CTAS, NT, SMEM_BYTES>>>(
        z_geo, z_tex, chart_w, chart_b, router_w, router_b, centers,
        tex_w, tex_b, ln_g, ln_b, w1, b1, w2, b2, out, B);
}